// round 13
// baseline (speedup 1.0000x reference)
#include <cuda_runtime.h>
#include <cuda_bf16.h>

#define NN 50000
#define EE 800000
#define ET 850000        // EE + NN self loops
#define IND 128
#define OUTD 128
#define HH 4
#define CC 32
#define PP 3
#define FEAT 768         // P * 2 * 128 (xl|xr per path)
#define NEGS 0.2f
#define LNEPS 1e-5f
#define SCANB 49         // ceil(NN/1024)

// ---------------- scratch (device globals; no allocation allowed) ----------
__device__ float g_feat[(size_t)NN * FEAT];        // [N][768]: p*256+c = xl_p, p*256+128+c = xr_p
__device__ float g_score[(size_t)PP * ET * HH];    // [P][slot][4], CSR-sorted order
__device__ int   g_off[NN + 1];
__device__ int   g_cursor[NN];
__device__ int   g_srcs[ET];                       // src per CSR slot
__device__ int   g_dsts[ET];                       // dst per CSR slot
__device__ int   g_bsum[64];                       // scan block sums
__device__ int   g_is64;                           // 1 if edge_index is int64, 0 if int32

// ---------------- dtype detection ------------------------------------------
__global__ void k_detect(const unsigned int* __restrict__ w) {
    __shared__ int bad;
    if (threadIdx.x == 0) bad = 0;
    __syncthreads();
    int mybad = 0;
    for (int i = 1 + 2 * threadIdx.x; i < 4096; i += 2 * 256)
        mybad |= (w[i] != 0u);
    if (mybad) atomicOr(&bad, 1);
    __syncthreads();
    if (threadIdx.x == 0) g_is64 = bad ? 0 : 1;
}

__device__ __forceinline__ int load_idx(const void* ei, size_t i, int is64) {
    return is64 ? (int)((const long long*)ei)[i] : ((const int*)ei)[i];
}

// ---------------- CSR build ------------------------------------------------
__global__ void k_zero() {
    int i = blockIdx.x * blockDim.x + threadIdx.x;
    if (i < NN) g_cursor[i] = 0;
}

__global__ void k_hist(const void* __restrict__ ei) {
    int e = blockIdx.x * blockDim.x + threadIdx.x;
    if (e >= ET) return;
    int is64 = g_is64;
    int dst = (e < EE) ? load_idx(ei, (size_t)EE + e, is64) : (e - EE);
    atomicAdd(&g_cursor[dst], 1);
}

// hierarchical exclusive scan
__global__ void k_scan1() {
    __shared__ int sm[1024];
    int b = blockIdx.x, t = threadIdx.x;
    int idx = b * 1024 + t;
    int v = (idx < NN) ? g_cursor[idx] : 0;
    sm[t] = v;
    __syncthreads();
#pragma unroll
    for (int off = 1; off < 1024; off <<= 1) {
        int u = (t >= off) ? sm[t - off] : 0;
        __syncthreads();
        sm[t] += u;
        __syncthreads();
    }
    if (idx < NN) g_off[idx] = sm[t] - v;
    if (t == 1023) g_bsum[b] = sm[1023];
}

__global__ void k_scan2() {
    __shared__ int sm[64];
    int t = threadIdx.x;
    int v = (t < SCANB) ? g_bsum[t] : 0;
    sm[t] = v;
    __syncthreads();
#pragma unroll
    for (int off = 1; off < 64; off <<= 1) {
        int u = (t >= off) ? sm[t - off] : 0;
        __syncthreads();
        sm[t] += u;
        __syncthreads();
    }
    if (t < SCANB) g_bsum[t] = sm[t] - v;
    if (t == SCANB - 1) g_off[NN] = sm[SCANB - 1];
}

__global__ void k_scan3() {
    int b = blockIdx.x, t = threadIdx.x;
    int idx = b * 1024 + t;
    if (idx < NN) {
        int o = g_off[idx] + g_bsum[b];
        g_off[idx] = o;
        g_cursor[idx] = o;
    }
}

__global__ void k_fill(const void* __restrict__ ei) {
    int e = blockIdx.x * blockDim.x + threadIdx.x;
    if (e >= ET) return;
    int is64 = g_is64;
    int src, dst;
    if (e < EE) {
        src = load_idx(ei, (size_t)e, is64);
        dst = load_idx(ei, (size_t)EE + e, is64);
    } else {
        src = dst = e - EE;
    }
    int pos = atomicAdd(&g_cursor[dst], 1);
    g_srcs[pos] = src;
    g_dsts[pos] = dst;
}

// ---------------- packed f32x2 helpers -------------------------------------
__device__ __forceinline__ void ffma2(unsigned long long& acc,
                                      unsigned long long a,
                                      unsigned long long b) {
    asm("fma.rn.f32x2 %0, %1, %2, %0;" : "+l"(acc) : "l"(a), "l"(b));
}
__device__ __forceinline__ float2 unpack2(unsigned long long u) {
    float2 f;
    asm("mov.b64 {%0, %1}, %2;" : "=f"(f.x), "=f"(f.y) : "l"(u));
    return f;
}

// ---------------- fused projection GEMM (f32x2 packed FFMA) ----------------
// g_feat = X @ [Wl0|Wr0|Wl1|Wr1|Wl2|Wr2] + bias; 64x64 tile, 4x4 micro tile.
__global__ void __launch_bounds__(256)
k_gemm(const float* __restrict__ x,
       const float* __restrict__ Wl, const float* __restrict__ bl,
       const float* __restrict__ Wr, const float* __restrict__ br) {
    __shared__ float As2[16][128];  // duplicated (a,a) pairs: [k][2*row{+0,1}]
    __shared__ float Bs[16][64];    // [k][col]
    int row0 = blockIdx.x * 64;
    int c0   = blockIdx.y * 64;
    int p    = c0 >> 8;
    int side = (c0 >> 7) & 1;
    int o0   = c0 & 127;
    const float* W    = (side ? Wr : Wl) + p * (IND * OUTD) + o0;
    const float* bias = (side ? br : bl) + p * OUTD + o0;

    int tid = threadIdx.x;         // 256
    int tx = tid & 15, ty = tid >> 4;

    unsigned long long acc2[4][2];
#pragma unroll
    for (int i = 0; i < 4; i++) { acc2[i][0] = 0ull; acc2[i][1] = 0ull; }

    for (int k0 = 0; k0 < IND; k0 += 16) {
        {   // load A tile (64 rows x 16 k), duplicated into As2[k][2r,2r+1]
            int r = tid >> 2, q = tid & 3;
            int row = row0 + r;
            float4 v = make_float4(0.f, 0.f, 0.f, 0.f);
            if (row < NN) v = *(const float4*)&x[(size_t)row * IND + k0 + q * 4];
            *(float2*)&As2[q * 4 + 0][2 * r] = make_float2(v.x, v.x);
            *(float2*)&As2[q * 4 + 1][2 * r] = make_float2(v.y, v.y);
            *(float2*)&As2[q * 4 + 2][2 * r] = make_float2(v.z, v.z);
            *(float2*)&As2[q * 4 + 3][2 * r] = make_float2(v.w, v.w);
        }
        {   // load B tile (16 k x 64 cols)
            int k = tid >> 4, q = tid & 15;
            float4 v = *(const float4*)&W[(size_t)(k0 + k) * OUTD + q * 4];
            *(float4*)&Bs[k][q * 4] = v;
        }
        __syncthreads();
#pragma unroll
        for (int kk = 0; kk < 16; kk++) {
            ulonglong2 Ad0 = *(const ulonglong2*)&As2[kk][ty * 8];      // (a0,a0),(a1,a1)
            ulonglong2 Ad1 = *(const ulonglong2*)&As2[kk][ty * 8 + 4];  // (a2,a2),(a3,a3)
            ulonglong2 Bd  = *(const ulonglong2*)&Bs[kk][tx * 4];       // (b0,b1),(b2,b3)
            ffma2(acc2[0][0], Ad0.x, Bd.x); ffma2(acc2[0][1], Ad0.x, Bd.y);
            ffma2(acc2[1][0], Ad0.y, Bd.x); ffma2(acc2[1][1], Ad0.y, Bd.y);
            ffma2(acc2[2][0], Ad1.x, Bd.x); ffma2(acc2[2][1], Ad1.x, Bd.y);
            ffma2(acc2[3][0], Ad1.y, Bd.x); ffma2(acc2[3][1], Ad1.y, Bd.y);
        }
        __syncthreads();
    }
    float4 bv = *(const float4*)&bias[tx * 4];
#pragma unroll
    for (int i = 0; i < 4; i++) {
        int row = row0 + ty * 4 + i;
        if (row < NN) {
            float2 lo = unpack2(acc2[i][0]);
            float2 hi = unpack2(acc2[i][1]);
            float4 o;
            o.x = lo.x + bv.x; o.y = lo.y + bv.y;
            o.z = hi.x + bv.z; o.w = hi.y + bv.w;
            *(float4*)&g_feat[(size_t)row * FEAT + c0 + tx * 4] = o;
        }
    }
}

// ---------------- edge scores: one warp per CSR slot, all 3 paths ----------
__global__ void __launch_bounds__(256, 8)
k_score(const float* __restrict__ att) {
    int warp = (blockIdx.x * blockDim.x + threadIdx.x) >> 5;
    int lane = threadIdx.x & 31;
    if (warp >= ET) return;
    int i = warp;
    int src = __ldg(&g_srcs[i]);
    int dst = __ldg(&g_dsts[i]);

    const float* fsrc = &g_feat[(size_t)src * FEAT];
    const float* fdst = &g_feat[(size_t)dst * FEAT];

#pragma unroll
    for (int p = 0; p < PP; p++) {
        float4 a = *(const float4*)&att[p * 128 + lane * 4];
        float4 l = *(const float4*)&fsrc[p * 256 + lane * 4];
        float4 r = *(const float4*)&fdst[p * 256 + 128 + lane * 4];

        float s = 0.f, u;
        u = l.x + r.x; s += (u > 0.f ? u : NEGS * u) * a.x;
        u = l.y + r.y; s += (u > 0.f ? u : NEGS * u) * a.y;
        u = l.z + r.z; s += (u > 0.f ? u : NEGS * u) * a.z;
        u = l.w + r.w; s += (u > 0.f ? u : NEGS * u) * a.w;

        s += __shfl_down_sync(0xffffffffu, s, 4);
        s += __shfl_down_sync(0xffffffffu, s, 2);
        s += __shfl_down_sync(0xffffffffu, s, 1);

        float s0 = __shfl_sync(0xffffffffu, s, 0);
        float s1 = __shfl_sync(0xffffffffu, s, 8);
        float s2 = __shfl_sync(0xffffffffu, s, 16);
        float s3 = __shfl_sync(0xffffffffu, s, 24);
        if (lane == 0) {
            *(float4*)&g_score[((size_t)p * ET + i) * 4] =
                make_float4(s0, s1, s2, s3);
        }
    }
}

// ---------------- per-destination softmax + aggregate ----------------------
__global__ void __launch_bounds__(256, 8)
k_agg(const float* __restrict__ out_bias,
      float* __restrict__ out) {
    int warp = (blockIdx.x * blockDim.x + threadIdx.x) >> 5;
    int lane = threadIdx.x & 31;
    if (warp >= NN) return;
    int n = warp;
    int p = blockIdx.y;
    int beg = g_off[n], end = g_off[n + 1];
    const float* score = &g_score[(size_t)p * ET * 4];

    float4 mx = make_float4(-3.4e38f, -3.4e38f, -3.4e38f, -3.4e38f);
    for (int i = beg + lane; i < end; i += 32) {
        float4 sc = *(const float4*)&score[(size_t)i * 4];
        mx.x = fmaxf(mx.x, sc.x); mx.y = fmaxf(mx.y, sc.y);
        mx.z = fmaxf(mx.z, sc.z); mx.w = fmaxf(mx.w, sc.w);
    }
#pragma unroll
    for (int o = 16; o > 0; o >>= 1) {
        mx.x = fmaxf(mx.x, __shfl_xor_sync(0xffffffffu, mx.x, o));
        mx.y = fmaxf(mx.y, __shfl_xor_sync(0xffffffffu, mx.y, o));
        mx.z = fmaxf(mx.z, __shfl_xor_sync(0xffffffffu, mx.z, o));
        mx.w = fmaxf(mx.w, __shfl_xor_sync(0xffffffffu, mx.w, o));
    }
    float4 se = make_float4(0.f, 0.f, 0.f, 0.f);
    for (int i = beg + lane; i < end; i += 32) {
        float4 sc = *(const float4*)&score[(size_t)i * 4];
        se.x += __expf(sc.x - mx.x); se.y += __expf(sc.y - mx.y);
        se.z += __expf(sc.z - mx.z); se.w += __expf(sc.w - mx.w);
    }
#pragma unroll
    for (int o = 16; o > 0; o >>= 1) {
        se.x += __shfl_xor_sync(0xffffffffu, se.x, o);
        se.y += __shfl_xor_sync(0xffffffffu, se.y, o);
        se.z += __shfl_xor_sync(0xffffffffu, se.z, o);
        se.w += __shfl_xor_sync(0xffffffffu, se.w, o);
    }
    int h = lane >> 3;
    float mxh = (h == 0) ? mx.x : (h == 1) ? mx.y : (h == 2) ? mx.z : mx.w;
    float seh = (h == 0) ? se.x : (h == 1) ? se.y : (h == 2) ? se.z : se.w;
    float sinv = 1.0f / seh;

    float4 acc = make_float4(0.f, 0.f, 0.f, 0.f);
    for (int i = beg; i < end; i++) {
        int src = __ldg(&g_srcs[i]);
        float sc = __ldg(&score[(size_t)i * 4 + h]);
        float w = __expf(sc - mxh) * sinv;
        float4 v = *(const float4*)&g_feat[(size_t)src * FEAT + p * 256 + lane * 4];
        acc.x += w * v.x; acc.y += w * v.y; acc.z += w * v.z; acc.w += w * v.w;
    }
    float4 b = *(const float4*)&out_bias[p * 128 + lane * 4];
    float4 o;
    o.x = fmaxf(acc.x + b.x, 0.f);
    o.y = fmaxf(acc.y + b.y, 0.f);
    o.z = fmaxf(acc.z + b.z, 0.f);
    o.w = fmaxf(acc.w + b.w, 0.f);
    *(float4*)&out[(size_t)n * (PP * OUTD) + p * 128 + lane * 4] = o;
}

// ---------------- in-place LayerNorm over 384-wide rows --------------------
__global__ void k_ln(float* __restrict__ out,
                     const float* __restrict__ gamma,
                     const float* __restrict__ beta) {
    __shared__ float ssum[4], ssq[4];
    int n = blockIdx.x;
    int t = threadIdx.x;
    float v0 = out[(size_t)n * 384 + t];
    float v1 = out[(size_t)n * 384 + 128 + t];
    float v2 = out[(size_t)n * 384 + 256 + t];
    float s = v0 + v1 + v2;
    float q = v0 * v0 + v1 * v1 + v2 * v2;
#pragma unroll
    for (int o = 16; o > 0; o >>= 1) {
        s += __shfl_xor_sync(0xffffffffu, s, o);
        q += __shfl_xor_sync(0xffffffffu, q, o);
    }
    int w = t >> 5;
    if ((t & 31) == 0) { ssum[w] = s; ssq[w] = q; }
    __syncthreads();
    float ts = ssum[0] + ssum[1] + ssum[2] + ssum[3];
    float tq = ssq[0] + ssq[1] + ssq[2] + ssq[3];
    float mean = ts * (1.0f / 384.0f);
    float var = tq * (1.0f / 384.0f) - mean * mean;
    var = fmaxf(var, 0.f);
    float rs = rsqrtf(var + LNEPS);
    out[(size_t)n * 384 + t]       = (v0 - mean) * rs * gamma[t]       + beta[t];
    out[(size_t)n * 384 + 128 + t] = (v1 - mean) * rs * gamma[128 + t] + beta[128 + t];
    out[(size_t)n * 384 + 256 + t] = (v2 - mean) * rs * gamma[256 + t] + beta[256 + t];
}

// ---------------- launcher -------------------------------------------------
extern "C" void kernel_launch(void* const* d_in, const int* in_sizes, int n_in,
                              void* d_out, int out_size) {
    const float* x    = (const float*)d_in[0];
    const void*  ei   = d_in[1];
    const float* Wl   = (const float*)d_in[2];
    const float* bl   = (const float*)d_in[3];
    const float* Wr   = (const float*)d_in[4];
    const float* br   = (const float*)d_in[5];
    const float* att  = (const float*)d_in[6];
    const float* ob   = (const float*)d_in[7];
    const float* gam  = (const float*)d_in[8];
    const float* bet  = (const float*)d_in[9];
    float* out = (float*)d_out;

    k_detect<<<1, 256>>>((const unsigned int*)ei);
    k_zero<<<(NN + 255) / 256, 256>>>();
    k_hist<<<(ET + 255) / 256, 256>>>(ei);
    k_scan1<<<SCANB, 1024>>>();
    k_scan2<<<1, 64>>>();
    k_scan3<<<SCANB, 1024>>>();
    k_fill<<<(ET + 255) / 256, 256>>>(ei);
    k_gemm<<<dim3((NN + 63) / 64, FEAT / 64), 256>>>(x, Wl, bl, Wr, br);
    k_score<<<(ET * 32 + 255) / 256, 256>>>(att);
    k_agg<<<dim3((NN * 32 + 255) / 256, PP), 256>>>(ob, out);
    k_ln<<<NN, 128>>>(out, gam, bet);
}

// round 15
// speedup vs baseline: 1.1342x; 1.1342x over previous
#include <cuda_runtime.h>
#include <cuda_bf16.h>

#define NN 50000
#define EE 800000
#define ET 850000        // EE + NN self loops
#define IND 128
#define OUTD 128
#define HH 4
#define CC 32
#define PP 3
#define FEAT 768         // P * 2 * 128 (xl|xr per path)
#define NEGS 0.2f
#define LNEPS 1e-5f
#define SCANB 49         // ceil(NN/1024)

// ---------------- scratch (device globals; no allocation allowed) ----------
__device__ float g_feat[(size_t)NN * FEAT];        // [N][768]: p*256+c = xl_p, p*256+128+c = xr_p
__device__ float g_score[(size_t)PP * ET * HH];    // [P][slot][4], CSR-sorted order
__device__ int   g_off[NN + 1];
__device__ int   g_cursor[NN];
__device__ int   g_srcs[ET];                       // src per CSR slot
__device__ int   g_dsts[ET];                       // dst per CSR slot
__device__ int   g_bsum[64];                       // scan block sums
__device__ int   g_is64;                           // 1 if edge_index is int64, 0 if int32

// ---------------- dtype detection ------------------------------------------
__global__ void k_detect(const unsigned int* __restrict__ w) {
    __shared__ int bad;
    if (threadIdx.x == 0) bad = 0;
    __syncthreads();
    int mybad = 0;
    for (int i = 1 + 2 * threadIdx.x; i < 4096; i += 2 * 256)
        mybad |= (w[i] != 0u);
    if (mybad) atomicOr(&bad, 1);
    __syncthreads();
    if (threadIdx.x == 0) g_is64 = bad ? 0 : 1;
}

__device__ __forceinline__ int load_idx(const void* ei, size_t i, int is64) {
    return is64 ? (int)((const long long*)ei)[i] : ((const int*)ei)[i];
}

// ---------------- CSR build ------------------------------------------------
__global__ void k_zero() {
    int i = blockIdx.x * blockDim.x + threadIdx.x;
    if (i < NN) g_cursor[i] = 0;
}

__global__ void k_hist(const void* __restrict__ ei) {
    int e = blockIdx.x * blockDim.x + threadIdx.x;
    if (e >= ET) return;
    int is64 = g_is64;
    int dst = (e < EE) ? load_idx(ei, (size_t)EE + e, is64) : (e - EE);
    atomicAdd(&g_cursor[dst], 1);
}

// hierarchical exclusive scan
__global__ void k_scan1() {
    __shared__ int sm[1024];
    int b = blockIdx.x, t = threadIdx.x;
    int idx = b * 1024 + t;
    int v = (idx < NN) ? g_cursor[idx] : 0;
    sm[t] = v;
    __syncthreads();
#pragma unroll
    for (int off = 1; off < 1024; off <<= 1) {
        int u = (t >= off) ? sm[t - off] : 0;
        __syncthreads();
        sm[t] += u;
        __syncthreads();
    }
    if (idx < NN) g_off[idx] = sm[t] - v;
    if (t == 1023) g_bsum[b] = sm[1023];
}

__global__ void k_scan2() {
    __shared__ int sm[64];
    int t = threadIdx.x;
    int v = (t < SCANB) ? g_bsum[t] : 0;
    sm[t] = v;
    __syncthreads();
#pragma unroll
    for (int off = 1; off < 64; off <<= 1) {
        int u = (t >= off) ? sm[t - off] : 0;
        __syncthreads();
        sm[t] += u;
        __syncthreads();
    }
    if (t < SCANB) g_bsum[t] = sm[t] - v;
    if (t == SCANB - 1) g_off[NN] = sm[SCANB - 1];
}

__global__ void k_scan3() {
    int b = blockIdx.x, t = threadIdx.x;
    int idx = b * 1024 + t;
    if (idx < NN) {
        int o = g_off[idx] + g_bsum[b];
        g_off[idx] = o;
        g_cursor[idx] = o;
    }
}

__global__ void k_fill(const void* __restrict__ ei) {
    int e = blockIdx.x * blockDim.x + threadIdx.x;
    if (e >= ET) return;
    int is64 = g_is64;
    int src, dst;
    if (e < EE) {
        src = load_idx(ei, (size_t)e, is64);
        dst = load_idx(ei, (size_t)EE + e, is64);
    } else {
        src = dst = e - EE;
    }
    int pos = atomicAdd(&g_cursor[dst], 1);
    g_srcs[pos] = src;
    g_dsts[pos] = dst;
}

// ---------------- fused projection GEMM: g_feat = X @ [Wl0|Wr0|Wl1|Wr1|Wl2|Wr2] + bias
// 64x64 tile, 4x4 per-thread micro tile, k-step 16. (proven scalar version)
__global__ void __launch_bounds__(256)
k_gemm(const float* __restrict__ x,
       const float* __restrict__ Wl, const float* __restrict__ bl,
       const float* __restrict__ Wr, const float* __restrict__ br) {
    __shared__ float As[16][64];   // [k][row]
    __shared__ float Bs[16][64];   // [k][col]
    int row0 = blockIdx.x * 64;
    int c0   = blockIdx.y * 64;
    int p    = c0 >> 8;
    int side = (c0 >> 7) & 1;
    int o0   = c0 & 127;
    const float* W    = (side ? Wr : Wl) + p * (IND * OUTD) + o0;
    const float* bias = (side ? br : bl) + p * OUTD + o0;

    int tid = threadIdx.x;         // 256
    int tx = tid & 15, ty = tid >> 4;

    float acc[4][4];
#pragma unroll
    for (int i = 0; i < 4; i++)
#pragma unroll
        for (int j = 0; j < 4; j++) acc[i][j] = 0.0f;

    for (int k0 = 0; k0 < IND; k0 += 16) {
        {   // load A tile (64 rows x 16 k), transpose into As[k][row]
            int r = tid >> 2, q = tid & 3;
            int row = row0 + r;
            float4 v = make_float4(0.f, 0.f, 0.f, 0.f);
            if (row < NN) v = *(const float4*)&x[(size_t)row * IND + k0 + q * 4];
            As[q * 4 + 0][r] = v.x;
            As[q * 4 + 1][r] = v.y;
            As[q * 4 + 2][r] = v.z;
            As[q * 4 + 3][r] = v.w;
        }
        {   // load B tile (16 k x 64 cols)
            int k = tid >> 4, q = tid & 15;
            float4 v = *(const float4*)&W[(size_t)(k0 + k) * OUTD + q * 4];
            *(float4*)&Bs[k][q * 4] = v;
        }
        __syncthreads();
#pragma unroll
        for (int kk = 0; kk < 16; kk++) {
            float4 a = *(float4*)&As[kk][ty * 4];
            float4 b = *(float4*)&Bs[kk][tx * 4];
            acc[0][0] += a.x * b.x; acc[0][1] += a.x * b.y; acc[0][2] += a.x * b.z; acc[0][3] += a.x * b.w;
            acc[1][0] += a.y * b.x; acc[1][1] += a.y * b.y; acc[1][2] += a.y * b.z; acc[1][3] += a.y * b.w;
            acc[2][0] += a.z * b.x; acc[2][1] += a.z * b.y; acc[2][2] += a.z * b.z; acc[2][3] += a.z * b.w;
            acc[3][0] += a.w * b.x; acc[3][1] += a.w * b.y; acc[3][2] += a.w * b.z; acc[3][3] += a.w * b.w;
        }
        __syncthreads();
    }
    float4 bv = *(const float4*)&bias[tx * 4];
#pragma unroll
    for (int i = 0; i < 4; i++) {
        int row = row0 + ty * 4 + i;
        if (row < NN) {
            float4 o;
            o.x = acc[i][0] + bv.x; o.y = acc[i][1] + bv.y;
            o.z = acc[i][2] + bv.z; o.w = acc[i][3] + bv.w;
            *(float4*)&g_feat[(size_t)row * FEAT + c0 + tx * 4] = o;
        }
    }
}

// ---------------- edge scores: one warp per CSR slot, all 3 paths ----------
__global__ void __launch_bounds__(256, 8)
k_score(const float* __restrict__ att) {
    int warp = (blockIdx.x * blockDim.x + threadIdx.x) >> 5;
    int lane = threadIdx.x & 31;
    if (warp >= ET) return;
    int i = warp;
    int src = __ldg(&g_srcs[i]);
    int dst = __ldg(&g_dsts[i]);

    const float* fsrc = &g_feat[(size_t)src * FEAT];
    const float* fdst = &g_feat[(size_t)dst * FEAT];

#pragma unroll
    for (int p = 0; p < PP; p++) {
        float4 a = *(const float4*)&att[p * 128 + lane * 4];
        float4 l = *(const float4*)&fsrc[p * 256 + lane * 4];
        float4 r = *(const float4*)&fdst[p * 256 + 128 + lane * 4];

        float s = 0.f, u;
        u = l.x + r.x; s += (u > 0.f ? u : NEGS * u) * a.x;
        u = l.y + r.y; s += (u > 0.f ? u : NEGS * u) * a.y;
        u = l.z + r.z; s += (u > 0.f ? u : NEGS * u) * a.z;
        u = l.w + r.w; s += (u > 0.f ? u : NEGS * u) * a.w;

        s += __shfl_down_sync(0xffffffffu, s, 4);
        s += __shfl_down_sync(0xffffffffu, s, 2);
        s += __shfl_down_sync(0xffffffffu, s, 1);

        float s0 = __shfl_sync(0xffffffffu, s, 0);
        float s1 = __shfl_sync(0xffffffffu, s, 8);
        float s2 = __shfl_sync(0xffffffffu, s, 16);
        float s3 = __shfl_sync(0xffffffffu, s, 24);
        if (lane == 0) {
            *(float4*)&g_score[((size_t)p * ET + i) * 4] =
                make_float4(s0, s1, s2, s3);
        }
    }
}

// ---------------- per-destination softmax + aggregate ----------------------
__global__ void __launch_bounds__(256, 8)
k_agg(const float* __restrict__ out_bias,
      float* __restrict__ out) {
    int warp = (blockIdx.x * blockDim.x + threadIdx.x) >> 5;
    int lane = threadIdx.x & 31;
    if (warp >= NN) return;
    int n = warp;
    int p = blockIdx.y;
    int beg = g_off[n], end = g_off[n + 1];
    const float* score = &g_score[(size_t)p * ET * 4];

    float4 mx = make_float4(-3.4e38f, -3.4e38f, -3.4e38f, -3.4e38f);
    for (int i = beg + lane; i < end; i += 32) {
        float4 sc = *(const float4*)&score[(size_t)i * 4];
        mx.x = fmaxf(mx.x, sc.x); mx.y = fmaxf(mx.y, sc.y);
        mx.z = fmaxf(mx.z, sc.z); mx.w = fmaxf(mx.w, sc.w);
    }
#pragma unroll
    for (int o = 16; o > 0; o >>= 1) {
        mx.x = fmaxf(mx.x, __shfl_xor_sync(0xffffffffu, mx.x, o));
        mx.y = fmaxf(mx.y, __shfl_xor_sync(0xffffffffu, mx.y, o));
        mx.z = fmaxf(mx.z, __shfl_xor_sync(0xffffffffu, mx.z, o));
        mx.w = fmaxf(mx.w, __shfl_xor_sync(0xffffffffu, mx.w, o));
    }
    float4 se = make_float4(0.f, 0.f, 0.f, 0.f);
    for (int i = beg + lane; i < end; i += 32) {
        float4 sc = *(const float4*)&score[(size_t)i * 4];
        se.x += __expf(sc.x - mx.x); se.y += __expf(sc.y - mx.y);
        se.z += __expf(sc.z - mx.z); se.w += __expf(sc.w - mx.w);
    }
#pragma unroll
    for (int o = 16; o > 0; o >>= 1) {
        se.x += __shfl_xor_sync(0xffffffffu, se.x, o);
        se.y += __shfl_xor_sync(0xffffffffu, se.y, o);
        se.z += __shfl_xor_sync(0xffffffffu, se.z, o);
        se.w += __shfl_xor_sync(0xffffffffu, se.w, o);
    }
    int h = lane >> 3;
    float mxh = (h == 0) ? mx.x : (h == 1) ? mx.y : (h == 2) ? mx.z : mx.w;
    float seh = (h == 0) ? se.x : (h == 1) ? se.y : (h == 2) ? se.z : se.w;
    float sinv = 1.0f / seh;

    float4 acc = make_float4(0.f, 0.f, 0.f, 0.f);
    for (int i = beg; i < end; i++) {
        int src = __ldg(&g_srcs[i]);
        float sc = __ldg(&score[(size_t)i * 4 + h]);
        float w = __expf(sc - mxh) * sinv;
        float4 v = *(const float4*)&g_feat[(size_t)src * FEAT + p * 256 + lane * 4];
        acc.x += w * v.x; acc.y += w * v.y; acc.z += w * v.z; acc.w += w * v.w;
    }
    float4 b = *(const float4*)&out_bias[p * 128 + lane * 4];
    float4 o;
    o.x = fmaxf(acc.x + b.x, 0.f);
    o.y = fmaxf(acc.y + b.y, 0.f);
    o.z = fmaxf(acc.z + b.z, 0.f);
    o.w = fmaxf(acc.w + b.w, 0.f);
    *(float4*)&out[(size_t)n * (PP * OUTD) + p * 128 + lane * 4] = o;
}

// ---------------- in-place LayerNorm over 384-wide rows --------------------
__global__ void k_ln(float* __restrict__ out,
                     const float* __restrict__ gamma,
                     const float* __restrict__ beta) {
    __shared__ float ssum[4], ssq[4];
    int n = blockIdx.x;
    int t = threadIdx.x;
    float v0 = out[(size_t)n * 384 + t];
    float v1 = out[(size_t)n * 384 + 128 + t];
    float v2 = out[(size_t)n * 384 + 256 + t];
    float s = v0 + v1 + v2;
    float q = v0 * v0 + v1 * v1 + v2 * v2;
#pragma unroll
    for (int o = 16; o > 0; o >>= 1) {
        s += __shfl_xor_sync(0xffffffffu, s, o);
        q += __shfl_xor_sync(0xffffffffu, q, o);
    }
    int w = t >> 5;
    if ((t & 31) == 0) { ssum[w] = s; ssq[w] = q; }
    __syncthreads();
    float ts = ssum[0] + ssum[1] + ssum[2] + ssum[3];
    float tq = ssq[0] + ssq[1] + ssq[2] + ssq[3];
    float mean = ts * (1.0f / 384.0f);
    float var = tq * (1.0f / 384.0f) - mean * mean;
    var = fmaxf(var, 0.f);
    float rs = rsqrtf(var + LNEPS);
    out[(size_t)n * 384 + t]       = (v0 - mean) * rs * gamma[t]       + beta[t];
    out[(size_t)n * 384 + 128 + t] = (v1 - mean) * rs * gamma[128 + t] + beta[128 + t];
    out[(size_t)n * 384 + 256 + t] = (v2 - mean) * rs * gamma[256 + t] + beta[256 + t];
}

// ---------------- launcher -------------------------------------------------
// NOTE: k_gemm moved to the 4th launch position (it has no CSR dependency)
// so the positional ncu capture window profiles it.
extern "C" void kernel_launch(void* const* d_in, const int* in_sizes, int n_in,
                              void* d_out, int out_size) {
    const float* x    = (const float*)d_in[0];
    const void*  ei   = d_in[1];
    const float* Wl   = (const float*)d_in[2];
    const float* bl   = (const float*)d_in[3];
    const float* Wr   = (const float*)d_in[4];
    const float* br   = (const float*)d_in[5];
    const float* att  = (const float*)d_in[6];
    const float* ob   = (const float*)d_in[7];
    const float* gam  = (const float*)d_in[8];
    const float* bet  = (const float*)d_in[9];
    float* out = (float*)d_out;

    k_detect<<<1, 256>>>((const unsigned int*)ei);
    k_zero<<<(NN + 255) / 256, 256>>>();
    k_hist<<<(ET + 255) / 256, 256>>>(ei);
    k_gemm<<<dim3((NN + 63) / 64, FEAT / 64), 256>>>(x, Wl, bl, Wr, br);   // 4th: profiled
    k_scan1<<<SCANB, 1024>>>();
    k_scan2<<<1, 64>>>();
    k_scan3<<<SCANB, 1024>>>();
    k_fill<<<(ET + 255) / 256, 256>>>(ei);
    k_score<<<(ET * 32 + 255) / 256, 256>>>(att);
    k_agg<<<dim3((NN * 32 + 255) / 256, PP), 256>>>(ob, out);
    k_ln<<<NN, 128>>>(out, gam, bet);
}

// round 17
// speedup vs baseline: 1.1491x; 1.0131x over previous
#include <cuda_runtime.h>
#include <cuda_bf16.h>

#define NN 50000
#define EE 800000
#define ET 850000        // EE + NN self loops
#define IND 128
#define OUTD 128
#define HH 4
#define CC 32
#define PP 3
#define FEAT 768         // P * 2 * 128 (xl|xr per path)
#define NEGS 0.2f
#define LNEPS 1e-5f
#define SCANB 49         // ceil(NN/1024)

// ---------------- scratch (device globals; no allocation allowed) ----------
__device__ float g_feat[(size_t)NN * FEAT];        // [N][768]: p*256+c = xl_p, p*256+128+c = xr_p
__device__ float g_score[(size_t)PP * ET * HH];    // [P][slot][4], CSR-sorted order
__device__ int   g_off[NN + 1];
__device__ int   g_cursor[NN];
__device__ int   g_srcs[ET];                       // src per CSR slot
__device__ int   g_dsts[ET];                       // dst per CSR slot
__device__ int   g_bsum[64];                       // scan block sums
__device__ int   g_is64;                           // 1 if edge_index is int64, 0 if int32

// ---------------- dtype detection ------------------------------------------
__global__ void k_detect(const unsigned int* __restrict__ w) {
    __shared__ int bad;
    if (threadIdx.x == 0) bad = 0;
    __syncthreads();
    int mybad = 0;
    for (int i = 1 + 2 * threadIdx.x; i < 4096; i += 2 * 256)
        mybad |= (w[i] != 0u);
    if (mybad) atomicOr(&bad, 1);
    __syncthreads();
    if (threadIdx.x == 0) g_is64 = bad ? 0 : 1;
}

__device__ __forceinline__ int load_idx(const void* ei, size_t i, int is64) {
    return is64 ? (int)((const long long*)ei)[i] : ((const int*)ei)[i];
}

// ---------------- CSR build ------------------------------------------------
__global__ void k_zero() {
    int i = blockIdx.x * blockDim.x + threadIdx.x;
    if (i < NN) g_cursor[i] = 0;
}

__global__ void k_hist(const void* __restrict__ ei) {
    int e = blockIdx.x * blockDim.x + threadIdx.x;
    if (e >= ET) return;
    int is64 = g_is64;
    int dst = (e < EE) ? load_idx(ei, (size_t)EE + e, is64) : (e - EE);
    atomicAdd(&g_cursor[dst], 1);
}

// hierarchical exclusive scan
__global__ void k_scan1() {
    __shared__ int sm[1024];
    int b = blockIdx.x, t = threadIdx.x;
    int idx = b * 1024 + t;
    int v = (idx < NN) ? g_cursor[idx] : 0;
    sm[t] = v;
    __syncthreads();
#pragma unroll
    for (int off = 1; off < 1024; off <<= 1) {
        int u = (t >= off) ? sm[t - off] : 0;
        __syncthreads();
        sm[t] += u;
        __syncthreads();
    }
    if (idx < NN) g_off[idx] = sm[t] - v;
    if (t == 1023) g_bsum[b] = sm[1023];
}

__global__ void k_scan2() {
    __shared__ int sm[64];
    int t = threadIdx.x;
    int v = (t < SCANB) ? g_bsum[t] : 0;
    sm[t] = v;
    __syncthreads();
#pragma unroll
    for (int off = 1; off < 64; off <<= 1) {
        int u = (t >= off) ? sm[t - off] : 0;
        __syncthreads();
        sm[t] += u;
        __syncthreads();
    }
    if (t < SCANB) g_bsum[t] = sm[t] - v;
    if (t == SCANB - 1) g_off[NN] = sm[SCANB - 1];
}

__global__ void k_scan3() {
    int b = blockIdx.x, t = threadIdx.x;
    int idx = b * 1024 + t;
    if (idx < NN) {
        int o = g_off[idx] + g_bsum[b];
        g_off[idx] = o;
        g_cursor[idx] = o;
    }
}

__global__ void k_fill(const void* __restrict__ ei) {
    int e = blockIdx.x * blockDim.x + threadIdx.x;
    if (e >= ET) return;
    int is64 = g_is64;
    int src, dst;
    if (e < EE) {
        src = load_idx(ei, (size_t)e, is64);
        dst = load_idx(ei, (size_t)EE + e, is64);
    } else {
        src = dst = e - EE;
    }
    int pos = atomicAdd(&g_cursor[dst], 1);
    g_srcs[pos] = src;
    g_dsts[pos] = dst;
}

// ---------------- fused projection GEMM: g_feat = X @ [Wl0|Wr0|Wl1|Wr1|Wl2|Wr2] + bias
// 64x64 tile, 4x4 per-thread micro tile, k-step 16.
// Measured 271.7us: at simultaneous fma-pipe + smem-crossbar roofline (~8cyc/warp-kk).
__global__ void __launch_bounds__(256)
k_gemm(const float* __restrict__ x,
       const float* __restrict__ Wl, const float* __restrict__ bl,
       const float* __restrict__ Wr, const float* __restrict__ br) {
    __shared__ float As[16][64];   // [k][row]
    __shared__ float Bs[16][64];   // [k][col]
    int row0 = blockIdx.x * 64;
    int c0   = blockIdx.y * 64;
    int p    = c0 >> 8;
    int side = (c0 >> 7) & 1;
    int o0   = c0 & 127;
    const float* W    = (side ? Wr : Wl) + p * (IND * OUTD) + o0;
    const float* bias = (side ? br : bl) + p * OUTD + o0;

    int tid = threadIdx.x;         // 256
    int tx = tid & 15, ty = tid >> 4;

    float acc[4][4];
#pragma unroll
    for (int i = 0; i < 4; i++)
#pragma unroll
        for (int j = 0; j < 4; j++) acc[i][j] = 0.0f;

    for (int k0 = 0; k0 < IND; k0 += 16) {
        {   // load A tile (64 rows x 16 k), transpose into As[k][row]
            int r = tid >> 2, q = tid & 3;
            int row = row0 + r;
            float4 v = make_float4(0.f, 0.f, 0.f, 0.f);
            if (row < NN) v = *(const float4*)&x[(size_t)row * IND + k0 + q * 4];
            As[q * 4 + 0][r] = v.x;
            As[q * 4 + 1][r] = v.y;
            As[q * 4 + 2][r] = v.z;
            As[q * 4 + 3][r] = v.w;
        }
        {   // load B tile (16 k x 64 cols)
            int k = tid >> 4, q = tid & 15;
            float4 v = *(const float4*)&W[(size_t)(k0 + k) * OUTD + q * 4];
            *(float4*)&Bs[k][q * 4] = v;
        }
        __syncthreads();
#pragma unroll
        for (int kk = 0; kk < 16; kk++) {
            float4 a = *(float4*)&As[kk][ty * 4];
            float4 b = *(float4*)&Bs[kk][tx * 4];
            acc[0][0] += a.x * b.x; acc[0][1] += a.x * b.y; acc[0][2] += a.x * b.z; acc[0][3] += a.x * b.w;
            acc[1][0] += a.y * b.x; acc[1][1] += a.y * b.y; acc[1][2] += a.y * b.z; acc[1][3] += a.y * b.w;
            acc[2][0] += a.z * b.x; acc[2][1] += a.z * b.y; acc[2][2] += a.z * b.z; acc[2][3] += a.z * b.w;
            acc[3][0] += a.w * b.x; acc[3][1] += a.w * b.y; acc[3][2] += a.w * b.z; acc[3][3] += a.w * b.w;
        }
        __syncthreads();
    }
    float4 bv = *(const float4*)&bias[tx * 4];
#pragma unroll
    for (int i = 0; i < 4; i++) {
        int row = row0 + ty * 4 + i;
        if (row < NN) {
            float4 o;
            o.x = acc[i][0] + bv.x; o.y = acc[i][1] + bv.y;
            o.z = acc[i][2] + bv.z; o.w = acc[i][3] + bv.w;
            *(float4*)&g_feat[(size_t)row * FEAT + c0 + tx * 4] = o;
        }
    }
}

// ---------------- edge scores: one warp per CSR slot, all 3 paths ----------
__global__ void __launch_bounds__(256, 8)
k_score(const float* __restrict__ att) {
    int warp = (blockIdx.x * blockDim.x + threadIdx.x) >> 5;
    int lane = threadIdx.x & 31;
    if (warp >= ET) return;
    int i = warp;
    int src = __ldg(&g_srcs[i]);
    int dst = __ldg(&g_dsts[i]);

    const float* fsrc = &g_feat[(size_t)src * FEAT];
    const float* fdst = &g_feat[(size_t)dst * FEAT];

#pragma unroll
    for (int p = 0; p < PP; p++) {
        float4 a = *(const float4*)&att[p * 128 + lane * 4];
        float4 l = *(const float4*)&fsrc[p * 256 + lane * 4];
        float4 r = *(const float4*)&fdst[p * 256 + 128 + lane * 4];

        float s = 0.f, u;
        u = l.x + r.x; s += (u > 0.f ? u : NEGS * u) * a.x;
        u = l.y + r.y; s += (u > 0.f ? u : NEGS * u) * a.y;
        u = l.z + r.z; s += (u > 0.f ? u : NEGS * u) * a.z;
        u = l.w + r.w; s += (u > 0.f ? u : NEGS * u) * a.w;

        s += __shfl_down_sync(0xffffffffu, s, 4);
        s += __shfl_down_sync(0xffffffffu, s, 2);
        s += __shfl_down_sync(0xffffffffu, s, 1);

        float s0 = __shfl_sync(0xffffffffu, s, 0);
        float s1 = __shfl_sync(0xffffffffu, s, 8);
        float s2 = __shfl_sync(0xffffffffu, s, 16);
        float s3 = __shfl_sync(0xffffffffu, s, 24);
        if (lane == 0) {
            *(float4*)&g_score[((size_t)p * ET + i) * 4] =
                make_float4(s0, s1, s2, s3);
        }
    }
}

// ---------------- per-destination softmax + aggregate ----------------------
// one warp per (node, path); blockIdx.y = path. Pass 3 unrolled x4 for MLP.
__global__ void __launch_bounds__(256, 8)
k_agg(const float* __restrict__ out_bias,
      float* __restrict__ out) {
    int warp = (blockIdx.x * blockDim.x + threadIdx.x) >> 5;
    int lane = threadIdx.x & 31;
    if (warp >= NN) return;
    int n = warp;
    int p = blockIdx.y;
    int beg = g_off[n], end = g_off[n + 1];
    const float* score = &g_score[(size_t)p * ET * 4];

    float4 mx = make_float4(-3.4e38f, -3.4e38f, -3.4e38f, -3.4e38f);
    for (int i = beg + lane; i < end; i += 32) {
        float4 sc = *(const float4*)&score[(size_t)i * 4];
        mx.x = fmaxf(mx.x, sc.x); mx.y = fmaxf(mx.y, sc.y);
        mx.z = fmaxf(mx.z, sc.z); mx.w = fmaxf(mx.w, sc.w);
    }
#pragma unroll
    for (int o = 16; o > 0; o >>= 1) {
        mx.x = fmaxf(mx.x, __shfl_xor_sync(0xffffffffu, mx.x, o));
        mx.y = fmaxf(mx.y, __shfl_xor_sync(0xffffffffu, mx.y, o));
        mx.z = fmaxf(mx.z, __shfl_xor_sync(0xffffffffu, mx.z, o));
        mx.w = fmaxf(mx.w, __shfl_xor_sync(0xffffffffu, mx.w, o));
    }
    float4 se = make_float4(0.f, 0.f, 0.f, 0.f);
    for (int i = beg + lane; i < end; i += 32) {
        float4 sc = *(const float4*)&score[(size_t)i * 4];
        se.x += __expf(sc.x - mx.x); se.y += __expf(sc.y - mx.y);
        se.z += __expf(sc.z - mx.z); se.w += __expf(sc.w - mx.w);
    }
#pragma unroll
    for (int o = 16; o > 0; o >>= 1) {
        se.x += __shfl_xor_sync(0xffffffffu, se.x, o);
        se.y += __shfl_xor_sync(0xffffffffu, se.y, o);
        se.z += __shfl_xor_sync(0xffffffffu, se.z, o);
        se.w += __shfl_xor_sync(0xffffffffu, se.w, o);
    }
    int h = lane >> 3;
    float mxh = (h == 0) ? mx.x : (h == 1) ? mx.y : (h == 2) ? mx.z : mx.w;
    float seh = (h == 0) ? se.x : (h == 1) ? se.y : (h == 2) ? se.z : se.w;
    float sinv = 1.0f / seh;
    const size_t fofs = (size_t)p * 256 + lane * 4;

    // pass 3: weighted aggregation, unrolled x4 (independent gathers -> MLP)
    float4 acc = make_float4(0.f, 0.f, 0.f, 0.f);
    int i = beg;
    for (; i + 4 <= end; i += 4) {
        int s0 = __ldg(&g_srcs[i]);
        int s1 = __ldg(&g_srcs[i + 1]);
        int s2 = __ldg(&g_srcs[i + 2]);
        int s3 = __ldg(&g_srcs[i + 3]);
        float c0 = __ldg(&score[(size_t)(i)     * 4 + h]);
        float c1 = __ldg(&score[(size_t)(i + 1) * 4 + h]);
        float c2 = __ldg(&score[(size_t)(i + 2) * 4 + h]);
        float c3 = __ldg(&score[(size_t)(i + 3) * 4 + h]);
        float4 v0 = *(const float4*)&g_feat[(size_t)s0 * FEAT + fofs];
        float4 v1 = *(const float4*)&g_feat[(size_t)s1 * FEAT + fofs];
        float4 v2 = *(const float4*)&g_feat[(size_t)s2 * FEAT + fofs];
        float4 v3 = *(const float4*)&g_feat[(size_t)s3 * FEAT + fofs];
        float w0 = __expf(c0 - mxh) * sinv;
        float w1 = __expf(c1 - mxh) * sinv;
        float w2 = __expf(c2 - mxh) * sinv;
        float w3 = __expf(c3 - mxh) * sinv;
        acc.x += w0 * v0.x + w1 * v1.x + w2 * v2.x + w3 * v3.x;
        acc.y += w0 * v0.y + w1 * v1.y + w2 * v2.y + w3 * v3.y;
        acc.z += w0 * v0.z + w1 * v1.z + w2 * v2.z + w3 * v3.z;
        acc.w += w0 * v0.w + w1 * v1.w + w2 * v2.w + w3 * v3.w;
    }
    for (; i < end; i++) {
        int src = __ldg(&g_srcs[i]);
        float sc = __ldg(&score[(size_t)i * 4 + h]);
        float w = __expf(sc - mxh) * sinv;
        float4 v = *(const float4*)&g_feat[(size_t)src * FEAT + fofs];
        acc.x += w * v.x; acc.y += w * v.y; acc.z += w * v.z; acc.w += w * v.w;
    }
    float4 b = *(const float4*)&out_bias[p * 128 + lane * 4];
    float4 o;
    o.x = fmaxf(acc.x + b.x, 0.f);
    o.y = fmaxf(acc.y + b.y, 0.f);
    o.z = fmaxf(acc.z + b.z, 0.f);
    o.w = fmaxf(acc.w + b.w, 0.f);
    *(float4*)&out[(size_t)n * (PP * OUTD) + p * 128 + lane * 4] = o;
}

// ---------------- in-place LayerNorm over 384-wide rows (float4) ----------
__global__ void k_ln(float* __restrict__ out,
                     const float* __restrict__ gamma,
                     const float* __restrict__ beta) {
    __shared__ float ssum[3], ssq[3];
    int n = blockIdx.x;
    int t = threadIdx.x;   // 96 threads, each owns 4 consecutive floats
    float4 v = *(const float4*)&out[(size_t)n * 384 + t * 4];
    float s = v.x + v.y + v.z + v.w;
    float q = v.x * v.x + v.y * v.y + v.z * v.z + v.w * v.w;
#pragma unroll
    for (int o = 16; o > 0; o >>= 1) {
        s += __shfl_xor_sync(0xffffffffu, s, o);
        q += __shfl_xor_sync(0xffffffffu, q, o);
    }
    int w = t >> 5;
    if ((t & 31) == 0) { ssum[w] = s; ssq[w] = q; }
    __syncthreads();
    float ts = ssum[0] + ssum[1] + ssum[2];
    float tq = ssq[0] + ssq[1] + ssq[2];
    float mean = ts * (1.0f / 384.0f);
    float var = tq * (1.0f / 384.0f) - mean * mean;
    var = fmaxf(var, 0.f);
    float rs = rsqrtf(var + LNEPS);
    float4 g = *(const float4*)&gamma[t * 4];
    float4 b = *(const float4*)&beta[t * 4];
    float4 o;
    o.x = (v.x - mean) * rs * g.x + b.x;
    o.y = (v.y - mean) * rs * g.y + b.y;
    o.z = (v.z - mean) * rs * g.z + b.z;
    o.w = (v.w - mean) * rs * g.w + b.w;
    *(float4*)&out[(size_t)n * 384 + t * 4] = o;
}

// ---------------- launcher -------------------------------------------------
// k_gemm stays at 4th launch position (positional ncu window).
extern "C" void kernel_launch(void* const* d_in, const int* in_sizes, int n_in,
                              void* d_out, int out_size) {
    const float* x    = (const float*)d_in[0];
    const void*  ei   = d_in[1];
    const float* Wl   = (const float*)d_in[2];
    const float* bl   = (const float*)d_in[3];
    const float* Wr   = (const float*)d_in[4];
    const float* br   = (const float*)d_in[5];
    const float* att  = (const float*)d_in[6];
    const float* ob   = (const float*)d_in[7];
    const float* gam  = (const float*)d_in[8];
    const float* bet  = (const float*)d_in[9];
    float* out = (float*)d_out;

    k_detect<<<1, 256>>>((const unsigned int*)ei);
    k_zero<<<(NN + 255) / 256, 256>>>();
    k_hist<<<(ET + 255) / 256, 256>>>(ei);
    k_gemm<<<dim3((NN + 63) / 64, FEAT / 64), 256>>>(x, Wl, bl, Wr, br);   // 4th: profiled
    k_scan1<<<SCANB, 1024>>>();
    k_scan2<<<1, 64>>>();
    k_scan3<<<SCANB, 1024>>>();
    k_fill<<<(ET + 255) / 256, 256>>>(ei);
    k_score<<<(ET * 32 + 255) / 256, 256>>>(att);
    k_agg<<<dim3((NN * 32 + 255) / 256, PP), 256>>>(ob, out);
    k_ln<<<NN, 96>>>(out, gam, bet);
}